// round 3
// baseline (speedup 1.0000x reference)
#include <cuda_runtime.h>
#include <cstdint>
#include <cstddef>

#define B_ 16
#define T_ 8192
#define D_ 256
#define MAXSEG 4096   // max segments per batch = ceil(T/2)
#define ROWS 32
#define LN_EPS 1e-5f

// Scratch (static device globals; no runtime allocation)
__device__ int   g_start[B_ * MAXSEG];
__device__ int   g_cnt[B_ * MAXSEG];
__device__ int   g_nseg[B_];
__device__ float g_empty[D_];

// ---------------------------------------------------------------------------
// Kernel D: the constant output row for empty segments = LayerNorm(b_proj)
// ---------------------------------------------------------------------------
__global__ void empty_row_kernel(const float* __restrict__ bproj,
                                 const float* __restrict__ gamma,
                                 const float* __restrict__ beta) {
    __shared__ float red[D_];
    int e = threadIdx.x;
    float v = bproj[e];
    red[e] = v; __syncthreads();
    for (int o = 128; o; o >>= 1) { if (e < o) red[e] += red[e + o]; __syncthreads(); }
    float mu = red[0] * (1.0f / D_);
    __syncthreads();
    float d = v - mu;
    red[e] = d * d; __syncthreads();
    for (int o = 128; o; o >>= 1) { if (e < o) red[e] += red[e + o]; __syncthreads(); }
    float var = red[0] * (1.0f / D_);
    g_empty[e] = d * rsqrtf(var + LN_EPS) * gamma[e] + beta[e];
}

// ---------------------------------------------------------------------------
// Kernel A: per-batch segment extraction (+ mask output).
// One block per batch, 256 threads, 32 tokens/thread via boundary bitmasks.
// Detects int32 vs int64 input_ids at runtime (values are 0..7: in int64 form
// every odd 32-bit word is zero; in int32 form they are random ids).
// ---------------------------------------------------------------------------
__global__ void seg_kernel(const unsigned int* __restrict__ idw,
                           float* __restrict__ mask_out) {
    __shared__ int            s_cnt[MAXSEG];
    __shared__ unsigned short s_start[MAXSEG];
    __shared__ int            sc[256];

    int b   = blockIdx.x;
    int tid = threadIdx.x;

    // dtype probe: odd words within the first 8192 words (valid in both modes)
    int probe = (int)(idw[tid * 32 + 1] != 0u);
    int is32  = __syncthreads_or(probe);

    for (int s = tid; s < MAXSEG; s += 256) s_cnt[s] = 0;
    __syncthreads();

    // boundary bitmask for this thread's 32 tokens
    unsigned int bm = 0;
    if (is32) {
        const unsigned int* p = idw + (size_t)b * T_ + tid * 32;
        #pragma unroll
        for (int i = 0; i < 32; i++) bm |= (p[i] == 0u) ? (1u << i) : 0u;
    } else {
        const unsigned long long* p =
            (const unsigned long long*)idw + (size_t)b * T_ + tid * 32;
        #pragma unroll
        for (int i = 0; i < 32; i++) bm |= (p[i] == 0ull) ? (1u << i) : 0u;
    }
    unsigned int prevb;
    if (tid == 0) prevb = 1u;
    else if (is32) prevb = (idw[(size_t)b * T_ + tid * 32 - 1] == 0u) ? 1u : 0u;
    else prevb = (((const unsigned long long*)idw)[(size_t)b * T_ + tid * 32 - 1] == 0ull) ? 1u : 0u;

    unsigned int startm = ~bm & ((bm << 1) | prevb);
    int c = __popc(startm);

    // block inclusive scan of per-thread start counts
    sc[tid] = c; __syncthreads();
    for (int o = 1; o < 256; o <<= 1) {
        int v = (tid >= o) ? sc[tid - o] : 0;
        __syncthreads();
        sc[tid] += v;
        __syncthreads();
    }
    int base  = sc[tid] - c;
    int total = sc[255];

    // assign tokens to segments
    int local = 0;
    #pragma unroll 1
    for (int i = 0; i < 32; i++) {
        bool st = (startm >> i) & 1u;
        if (st) local++;
        if (!((bm >> i) & 1u)) {
            int s = base + local - 1;
            atomicAdd(&s_cnt[s], 1);
            if (st) s_start[s] = (unsigned short)(tid * 32 + i);
        }
    }
    __syncthreads();

    if (tid == 0) g_nseg[b] = total;
    for (int s = tid; s < total; s += 256) {
        g_start[b * MAXSEG + s] = (int)s_start[s];
        g_cnt[b * MAXSEG + s]   = s_cnt[s];
    }
    // mask: segments are created in order, every created segment has count>=1
    for (int w = tid; w < T_; w += 256)
        mask_out[(size_t)b * T_ + w] = (w < total) ? 1.0f : 0.0f;
}

// ---------------------------------------------------------------------------
// Kernel C: fused pooling + GEMM (out = P @ W^T + b) + LayerNorm + fill.
// Block = 32 segment rows of one batch; 256 threads.
// Rows past nseg get the precomputed constant row (single pass over output).
// ---------------------------------------------------------------------------
__global__ void __launch_bounds__(256)
fused_kernel(const float* __restrict__ x, const float* __restrict__ W,
             const float* __restrict__ bproj, const float* __restrict__ gamma,
             const float* __restrict__ beta, float* __restrict__ out) {
    __shared__ __align__(16) float P[ROWS * D_];
    __shared__ int   t0s[ROWS], cns[ROWS];
    __shared__ float smu[ROWS], srs[ROWS];

    int b  = blockIdx.y;
    int s0 = blockIdx.x * ROWS;
    int e  = threadIdx.x;

    int nseg = g_nseg[b];
    int nact = nseg - s0; if (nact > ROWS) nact = ROWS;

    float  ev = g_empty[e];
    float* op = out + ((size_t)(b * T_ + s0)) * D_ + e;

    if (nact <= 0) {  // pure fill block
        #pragma unroll
        for (int r = 0; r < ROWS; r++) op[r * D_] = ev;
        return;
    }

    if (e < ROWS) {
        if (e < nact) {
            t0s[e] = g_start[b * MAXSEG + s0 + e];
            cns[e] = g_cnt[b * MAXSEG + s0 + e];
        } else cns[e] = 0;
    }
    __syncthreads();

    // Phase 1: segment-mean pooling. thread index = channel d.
    {
        int d = e;
        for (int r = 0; r < ROWS; r++) {
            int   cnt = cns[r];
            float m   = 0.0f;
            if (cnt > 0) {
                const float* xp = x + ((size_t)b * T_ + t0s[r]) * D_ + d;
                float a0 = 0.f, a1 = 0.f, a2 = 0.f, a3 = 0.f;
                int k = 0;
                for (; k + 4 <= cnt; k += 4) {
                    a0 += xp[(size_t)(k + 0) * D_];
                    a1 += xp[(size_t)(k + 1) * D_];
                    a2 += xp[(size_t)(k + 2) * D_];
                    a3 += xp[(size_t)(k + 3) * D_];
                }
                for (; k < cnt; k++) a0 += xp[(size_t)k * D_];
                m = (a0 + a1 + a2 + a3) / (float)cnt;
            }
            P[r * D_ + d] = m;  // zero for inactive rows
        }
    }
    __syncthreads();

    // Phase 2: out[r][e] = sum_d P[r][d] * W[e][d] + b[e]. thread = e.
    float acc[ROWS];
    float bias = bproj[e];
    #pragma unroll
    for (int r = 0; r < ROWS; r++) acc[r] = bias;

    const float4* W4 = reinterpret_cast<const float4*>(W + (size_t)e * D_);
    #pragma unroll 4
    for (int q = 0; q < D_ / 4; q++) {
        float4 w = W4[q];
        #pragma unroll
        for (int r = 0; r < ROWS; r++) {
            float4 p = *reinterpret_cast<const float4*>(&P[r * D_ + q * 4]);
            acc[r] = fmaf(p.x, w.x, acc[r]);
            acc[r] = fmaf(p.y, w.y, acc[r]);
            acc[r] = fmaf(p.z, w.z, acc[r]);
            acc[r] = fmaf(p.w, w.w, acc[r]);
        }
    }
    __syncthreads();           // all threads done reading P

    // Phase 3: LayerNorm. Stash tile, warp-reduce per-row mean/var.
    #pragma unroll
    for (int r = 0; r < ROWS; r++) P[r * D_ + e] = acc[r];
    __syncthreads();

    int wid = e >> 5, lane = e & 31;
    for (int r = wid; r < ROWS; r += 8) {
        float s = 0.f, s2 = 0.f;
        #pragma unroll
        for (int j = 0; j < D_ / 32; j++) {
            float v = P[r * D_ + lane + 32 * j];
            s += v; s2 += v * v;
        }
        #pragma unroll
        for (int o = 16; o; o >>= 1) {
            s  += __shfl_xor_sync(0xffffffffu, s,  o);
            s2 += __shfl_xor_sync(0xffffffffu, s2, o);
        }
        if (lane == 0) {
            float mu  = s * (1.0f / D_);
            float var = fmaxf(s2 * (1.0f / D_) - mu * mu, 0.0f);
            smu[r] = mu;
            srs[r] = rsqrtf(var + LN_EPS);
        }
    }
    __syncthreads();

    float ga = gamma[e], be = beta[e];
    #pragma unroll
    for (int r = 0; r < ROWS; r++) {
        float v = (r < nact) ? (acc[r] - smu[r]) * srs[r] * ga + be : ev;
        op[r * D_] = v;
    }
}

// ---------------------------------------------------------------------------
// Inputs (metadata order): x f32[16,8192,256], input_ids int64/int32[16,8192],
// W_proj f32[256,256], b_proj f32[256], gamma f32[256], beta f32[256].
// Output: concat(out f32[16,8192,256], mask f32[16,8192]).
// ---------------------------------------------------------------------------
extern "C" void kernel_launch(void* const* d_in, const int* in_sizes, int n_in,
                              void* d_out, int out_size) {
    (void)in_sizes; (void)n_in; (void)out_size;
    const float*        x   = (const float*)d_in[0];
    const unsigned int* ids = (const unsigned int*)d_in[1];
    const float*        W   = (const float*)d_in[2];
    const float*        bp  = (const float*)d_in[3];
    const float*        ga  = (const float*)d_in[4];
    const float*        be  = (const float*)d_in[5];
    float* out  = (float*)d_out;
    float* mask = out + (size_t)B_ * T_ * D_;

    empty_row_kernel<<<1, 256>>>(bp, ga, be);
    seg_kernel<<<B_, 256>>>(ids, mask);
    fused_kernel<<<dim3(T_ / ROWS, B_), 256>>>(x, W, bp, ga, be, out);
}

// round 4
// speedup vs baseline: 1.2521x; 1.2521x over previous
#include <cuda_runtime.h>
#include <cstdint>
#include <cstddef>

#define B_ 16
#define T_ 8192
#define D_ 256
#define MAXSEG 4096   // max segments per batch = ceil(T/2)
#define ROWS 32
#define LN_EPS 1e-5f

// Scratch (static device globals; no runtime allocation)
__device__ int g_start[B_ * MAXSEG];
__device__ int g_cnt[B_ * MAXSEG];
__device__ int g_nseg[B_];

// packed f32x2 FMA (sm_100+; ptxas never auto-fuses — PTX only)
__device__ __forceinline__ void ffma2(unsigned long long& d,
                                      unsigned long long a,
                                      unsigned long long b) {
    asm("fma.rn.f32x2 %0, %1, %2, %0;" : "+l"(d) : "l"(a), "l"(b));
}

__device__ __forceinline__ void add4(float4& a, float4 v) {
    a.x += v.x; a.y += v.y; a.z += v.z; a.w += v.w;
}

// ---------------------------------------------------------------------------
// Kernel A: per-batch segment extraction (+ mask output). One block per batch.
// Boundary bitmask per thread (32 tokens); counts via next-set-bit search in
// a shared bitmask array (no atomics). Runtime int32/int64 dtype probe.
// ---------------------------------------------------------------------------
__global__ void seg_kernel(const unsigned int* __restrict__ idw,
                           float* __restrict__ mask_out) {
    __shared__ unsigned int s_bm[256];
    __shared__ int sc[256];

    int b   = blockIdx.x;
    int tid = threadIdx.x;

    // dtype probe: for int64 ids in [0,8), every odd 32-bit word is zero.
    int probe = (int)(idw[tid * 32 + 1] != 0u);
    int is32  = __syncthreads_or(probe);

    // boundary bitmask for this thread's 32 tokens
    unsigned int bm = 0;
    if (is32) {
        const uint4* p = (const uint4*)(idw + (size_t)b * T_ + tid * 32);
        #pragma unroll
        for (int i = 0; i < 8; i++) {
            uint4 v = p[i];
            bm |= (unsigned)(v.x == 0u) << (4 * i);
            bm |= (unsigned)(v.y == 0u) << (4 * i + 1);
            bm |= (unsigned)(v.z == 0u) << (4 * i + 2);
            bm |= (unsigned)(v.w == 0u) << (4 * i + 3);
        }
    } else {
        const ulonglong2* p = (const ulonglong2*)
            ((const unsigned long long*)idw + (size_t)b * T_ + tid * 32);
        #pragma unroll
        for (int i = 0; i < 16; i++) {
            ulonglong2 v = p[i];
            bm |= (unsigned)(v.x == 0ull) << (2 * i);
            bm |= (unsigned)(v.y == 0ull) << (2 * i + 1);
        }
    }
    s_bm[tid] = bm;
    __syncthreads();

    unsigned int prevb  = (tid == 0) ? 1u : (s_bm[tid - 1] >> 31);
    unsigned int startm = ~bm & ((bm << 1) | prevb);
    int c = __popc(startm);

    // block inclusive scan of per-thread start counts
    sc[tid] = c; __syncthreads();
    for (int o = 1; o < 256; o <<= 1) {
        int v = (tid >= o) ? sc[tid - o] : 0;
        __syncthreads();
        sc[tid] += v;
        __syncthreads();
    }
    int base  = sc[tid] - c;
    int total = sc[255];

    // emit (start, count) per segment: count = next boundary - start
    unsigned int m = startm;
    int local = 0;
    while (m) {
        int i = __ffs(m) - 1; m &= m - 1;
        int pos = tid * 32 + i;
        unsigned int w = (i < 31) ? (bm & (0xFFFFFFFEu << i)) : 0u;
        int j = tid;
        while (w == 0u && ++j < 256) w = s_bm[j];
        int nb = w ? (j * 32 + __ffs(w) - 1) : T_;
        int s  = base + (local++);
        g_start[b * MAXSEG + s] = pos;
        g_cnt[b * MAXSEG + s]   = nb - pos;
    }
    if (tid == 0) g_nseg[b] = total;

    // mask: 1.0 for w < total
    float4* m4 = (float4*)(mask_out + (size_t)b * T_);
    for (int q = tid; q < T_ / 4; q += 256) {
        int w0 = 4 * q;
        float4 v;
        v.x = (w0     < total) ? 1.0f : 0.0f;
        v.y = (w0 + 1 < total) ? 1.0f : 0.0f;
        v.z = (w0 + 2 < total) ? 1.0f : 0.0f;
        v.w = (w0 + 3 < total) ? 1.0f : 0.0f;
        m4[q] = v;
    }
}

// ---------------------------------------------------------------------------
// Kernel B: fused pooling + GEMM (FFMA2) + LayerNorm + constant-row fill.
// Block = 32 segment rows of one batch; 256 threads.
// ---------------------------------------------------------------------------
__global__ void __launch_bounds__(256)
fused_kernel(const float* __restrict__ x, const float* __restrict__ W,
             const float* __restrict__ bproj, const float* __restrict__ gamma,
             const float* __restrict__ beta, float* __restrict__ out) {
    __shared__ __align__(16) float P[ROWS * D_];
    __shared__ __align__(16) float evs[D_];
    __shared__ float smu[ROWS], srs[ROWS];
    __shared__ int   t0s[ROWS], cns[ROWS];
    __shared__ float wred[16];

    int b    = blockIdx.y;
    int s0   = blockIdx.x * ROWS;
    int e    = threadIdx.x;
    int lane = e & 31, wid = e >> 5;
    int c    = e & 63;     // channel quad 0..63
    int r0   = e >> 6;     // row group 0..3

    // ---- inline empty-row value: LN(b_proj) ----
    float bv = bproj[e];
    float ga = gamma[e], be = beta[e];
    {
        float s = bv, s2 = bv * bv;
        #pragma unroll
        for (int o = 16; o; o >>= 1) {
            s  += __shfl_xor_sync(0xffffffffu, s,  o);
            s2 += __shfl_xor_sync(0xffffffffu, s2, o);
        }
        if (lane == 0) { wred[wid] = s; wred[8 + wid] = s2; }
    }
    __syncthreads();
    {
        float ts = 0.f, ts2 = 0.f;
        #pragma unroll
        for (int i = 0; i < 8; i++) { ts += wred[i]; ts2 += wred[8 + i]; }
        float mu0  = ts * (1.0f / D_);
        float var0 = fmaxf(ts2 * (1.0f / D_) - mu0 * mu0, 0.0f);
        evs[e] = (bv - mu0) * rsqrtf(var0 + LN_EPS) * ga + be;
    }

    int nseg = g_nseg[b];
    int nact = nseg - s0; if (nact > ROWS) nact = ROWS;

    float4* out4 = (float4*)(out + ((size_t)(b * T_ + s0)) * D_);

    if (nact <= 0) {  // pure fill block: broadcast constant row, STG.128
        __syncthreads();
        float4 e4 = *(const float4*)&evs[4 * c];
        #pragma unroll
        for (int r = r0; r < ROWS; r += 4) out4[r * 64 + c] = e4;
        return;
    }

    if (e < ROWS) {
        if (e < nact) {
            t0s[e] = g_start[b * MAXSEG + s0 + e];
            cns[e] = g_cnt[b * MAXSEG + s0 + e];
        } else { t0s[e] = 0; cns[e] = 0; }
    }
    __syncthreads();

    // ---- Phase 1: segment-mean pooling (float4 streaming loads) ----
    for (int r = r0; r < ROWS; r += 4) {
        int cnt = cns[r];
        const float4* xp =
            (const float4*)(x + ((size_t)b * T_ + t0s[r]) * D_) + c;
        float4 a0 = {0,0,0,0}, a1 = {0,0,0,0}, a2 = {0,0,0,0}, a3 = {0,0,0,0};
        int k = 0;
        for (; k + 4 <= cnt; k += 4) {
            add4(a0, __ldcs(xp + (size_t)(k + 0) * 64));
            add4(a1, __ldcs(xp + (size_t)(k + 1) * 64));
            add4(a2, __ldcs(xp + (size_t)(k + 2) * 64));
            add4(a3, __ldcs(xp + (size_t)(k + 3) * 64));
        }
        for (; k < cnt; k++) add4(a0, __ldcs(xp + (size_t)k * 64));
        float inv = 1.0f / (float)(cnt > 0 ? cnt : 1);
        float4 mres;
        mres.x = (a0.x + a1.x + a2.x + a3.x) * inv;
        mres.y = (a0.y + a1.y + a2.y + a3.y) * inv;
        mres.z = (a0.z + a1.z + a2.z + a3.z) * inv;
        mres.w = (a0.w + a1.w + a2.w + a3.w) * inv;
        *(float4*)&P[r * D_ + 4 * c] = mres;   // zeros for inactive rows
    }
    __syncthreads();

    // ---- Phase 2: out[r][e] = P[r][:] . W[e][:] + b[e], packed f32x2 ----
    // acc2[r] holds (even-d partial, odd-d partial); bias seeded in lane 0.
    unsigned long long acc2[ROWS];
    unsigned long long binit = (unsigned long long)__float_as_uint(bv);
    #pragma unroll
    for (int r = 0; r < ROWS; r++) acc2[r] = binit;

    const ulonglong2* W2 = (const ulonglong2*)(W + (size_t)e * D_);
    #pragma unroll 1
    for (int q = 0; q < D_ / 4; q++) {
        ulonglong2 wv = W2[q];                         // (w0,w1),(w2,w3)
        const ulonglong2* Pq = (const ulonglong2*)&P[q * 4];
        #pragma unroll
        for (int r = 0; r < ROWS; r++) {
            ulonglong2 pv = Pq[r * (D_ / 4)];          // LDS.128 broadcast
            ffma2(acc2[r], pv.x, wv.x);
            ffma2(acc2[r], pv.y, wv.y);
        }
    }
    __syncthreads();   // everyone done reading P before overwrite

    // ---- Phase 3: stash, LN stats, vectorized store ----
    #pragma unroll
    for (int r = 0; r < ROWS; r++) {
        unsigned long long a = acc2[r];
        P[r * D_ + e] = __uint_as_float((unsigned)a) +
                        __uint_as_float((unsigned)(a >> 32));
    }
    __syncthreads();

    for (int r = wid; r < ROWS; r += 8) {
        float ss = 0.f, ss2 = 0.f;
        #pragma unroll
        for (int j = 0; j < D_ / 32; j++) {
            float v = P[r * D_ + lane + 32 * j];
            ss += v; ss2 += v * v;
        }
        #pragma unroll
        for (int o = 16; o; o >>= 1) {
            ss  += __shfl_xor_sync(0xffffffffu, ss,  o);
            ss2 += __shfl_xor_sync(0xffffffffu, ss2, o);
        }
        if (lane == 0) {
            float m  = ss * (1.0f / D_);
            float va = fmaxf(ss2 * (1.0f / D_) - m * m, 0.0f);
            smu[r] = m;
            srs[r] = rsqrtf(va + LN_EPS);
        }
    }
    __syncthreads();

    float4 g4 = ((const float4*)gamma)[c];
    float4 b4 = ((const float4*)beta)[c];
    float4 e4 = *(const float4*)&evs[4 * c];
    for (int r = r0; r < ROWS; r += 4) {
        float4 o4;
        if (r < nact) {
            float4 p4 = *(const float4*)&P[r * D_ + 4 * c];
            float m = smu[r], rs = srs[r];
            o4.x = (p4.x - m) * rs * g4.x + b4.x;
            o4.y = (p4.y - m) * rs * g4.y + b4.y;
            o4.z = (p4.z - m) * rs * g4.z + b4.z;
            o4.w = (p4.w - m) * rs * g4.w + b4.w;
        } else {
            o4 = e4;
        }
        out4[r * 64 + c] = o4;
    }
}

// ---------------------------------------------------------------------------
// Inputs (metadata order): x f32[16,8192,256], input_ids int64/int32[16,8192],
// W_proj f32[256,256], b_proj f32[256], gamma f32[256], beta f32[256].
// Output: concat(out f32[16,8192,256], mask f32[16,8192]).
// ---------------------------------------------------------------------------
extern "C" void kernel_launch(void* const* d_in, const int* in_sizes, int n_in,
                              void* d_out, int out_size) {
    (void)in_sizes; (void)n_in; (void)out_size;
    const float*        x   = (const float*)d_in[0];
    const unsigned int* ids = (const unsigned int*)d_in[1];
    const float*        W   = (const float*)d_in[2];
    const float*        bp  = (const float*)d_in[3];
    const float*        ga  = (const float*)d_in[4];
    const float*        be  = (const float*)d_in[5];
    float* out  = (float*)d_out;
    float* mask = out + (size_t)B_ * T_ * D_;

    seg_kernel<<<B_, 256>>>(ids, mask);
    fused_kernel<<<dim3(T_ / ROWS, B_), 256>>>(x, W, bp, ga, be, out);
}

// round 5
// speedup vs baseline: 1.3250x; 1.0582x over previous
#include <cuda_runtime.h>
#include <cstdint>
#include <cstddef>

#define B_ 16
#define T_ 8192
#define D_ 256
#define MAXSEG 4096   // max segments per batch = ceil(T/2)
#define ROWS 32
#define NTILE 8       // tiles per fused block
#define GX 32         // blocks per batch in x  (GX*NTILE*ROWS == T_)
#define LN_EPS 1e-5f

// Scratch (static device globals; no runtime allocation)
__device__ int g_start[B_ * MAXSEG];
__device__ int g_cnt[B_ * MAXSEG];
__device__ int g_nseg[B_];

// packed f32x2 FMA (sm_100+; ptxas never auto-fuses — PTX only)
__device__ __forceinline__ void ffma2(unsigned long long& d,
                                      unsigned long long a,
                                      unsigned long long b) {
    asm("fma.rn.f32x2 %0, %1, %2, %0;" : "+l"(d) : "l"(a), "l"(b));
}

__device__ __forceinline__ void add4(float4& a, float4 v) {
    a.x += v.x; a.y += v.y; a.z += v.z; a.w += v.w;
}

// ---------------------------------------------------------------------------
// Kernel A: per-batch segment extraction. One block per batch, 256 threads.
// Boundary bitmask per thread (32 tokens); counts via next-set-bit search.
// Runtime int32/int64 dtype probe. (mask output moved to fused_kernel)
// ---------------------------------------------------------------------------
__global__ void seg_kernel(const unsigned int* __restrict__ idw) {
    __shared__ unsigned int s_bm[256];
    __shared__ int sc[256];

    int b   = blockIdx.x;
    int tid = threadIdx.x;

    // dtype probe: for int64 ids in [0,8), every odd 32-bit word is zero.
    int probe = (int)(idw[tid * 32 + 1] != 0u);
    int is32  = __syncthreads_or(probe);

    unsigned int bm = 0;
    if (is32) {
        const uint4* p = (const uint4*)(idw + (size_t)b * T_ + tid * 32);
        #pragma unroll
        for (int i = 0; i < 8; i++) {
            uint4 v = p[i];
            bm |= (unsigned)(v.x == 0u) << (4 * i);
            bm |= (unsigned)(v.y == 0u) << (4 * i + 1);
            bm |= (unsigned)(v.z == 0u) << (4 * i + 2);
            bm |= (unsigned)(v.w == 0u) << (4 * i + 3);
        }
    } else {
        const ulonglong2* p = (const ulonglong2*)
            ((const unsigned long long*)idw + (size_t)b * T_ + tid * 32);
        #pragma unroll
        for (int i = 0; i < 16; i++) {
            ulonglong2 v = p[i];
            bm |= (unsigned)(v.x == 0ull) << (2 * i);
            bm |= (unsigned)(v.y == 0ull) << (2 * i + 1);
        }
    }
    s_bm[tid] = bm;
    __syncthreads();

    unsigned int prevb  = (tid == 0) ? 1u : (s_bm[tid - 1] >> 31);
    unsigned int startm = ~bm & ((bm << 1) | prevb);
    int c = __popc(startm);

    sc[tid] = c; __syncthreads();
    for (int o = 1; o < 256; o <<= 1) {
        int v = (tid >= o) ? sc[tid - o] : 0;
        __syncthreads();
        sc[tid] += v;
        __syncthreads();
    }
    int base  = sc[tid] - c;
    int total = sc[255];

    unsigned int m = startm;
    int local = 0;
    while (m) {
        int i = __ffs(m) - 1; m &= m - 1;
        int pos = tid * 32 + i;
        unsigned int w = (i < 31) ? (bm & (0xFFFFFFFEu << i)) : 0u;
        int j = tid;
        while (w == 0u && ++j < 256) w = s_bm[j];
        int nb = w ? (j * 32 + __ffs(w) - 1) : T_;
        int s  = base + (local++);
        g_start[b * MAXSEG + s] = pos;
        g_cnt[b * MAXSEG + s]   = nb - pos;
    }
    if (tid == 0) g_nseg[b] = total;
}

// ---------------------------------------------------------------------------
// Kernel B: fused pooling + GEMM (FFMA2) + LayerNorm + fill + mask.
// Block = NTILE strided tiles of ROWS segment rows each; 256 threads.
// Fill tiles processed FIRST (fire-and-forget STG.128), then active tiles,
// so fill bandwidth overlaps pooling/GEMM latency.
// ---------------------------------------------------------------------------
__global__ void __launch_bounds__(256, 2)
fused_kernel(const float* __restrict__ x, const float* __restrict__ W,
             const float* __restrict__ bproj, const float* __restrict__ gamma,
             const float* __restrict__ beta, float* __restrict__ out,
             float* __restrict__ mask_out) {
    __shared__ __align__(16) float P[ROWS * D_];
    __shared__ __align__(16) float evs[D_];
    __shared__ float smu[ROWS], srs[ROWS];
    __shared__ int   t0s[ROWS], cns[ROWS];
    __shared__ float wred[16];

    int b    = blockIdx.y;
    int bx   = blockIdx.x;
    int e    = threadIdx.x;
    int lane = e & 31, wid = e >> 5;
    int c    = e & 63;     // channel quad 0..63
    int r0   = e >> 6;     // row group 0..3

    // ---- inline empty-row value: LN(b_proj) ----
    float bv = bproj[e];
    {
        float s = bv, s2 = bv * bv;
        #pragma unroll
        for (int o = 16; o; o >>= 1) {
            s  += __shfl_xor_sync(0xffffffffu, s,  o);
            s2 += __shfl_xor_sync(0xffffffffu, s2, o);
        }
        if (lane == 0) { wred[wid] = s; wred[8 + wid] = s2; }
    }
    __syncthreads();
    {
        float ts = 0.f, ts2 = 0.f;
        #pragma unroll
        for (int i = 0; i < 8; i++) { ts += wred[i]; ts2 += wred[8 + i]; }
        float mu0  = ts * (1.0f / D_);
        float var0 = fmaxf(ts2 * (1.0f / D_) - mu0 * mu0, 0.0f);
        evs[e] = (bv - mu0) * rsqrtf(var0 + LN_EPS) * gamma[e] + beta[e];
    }
    __syncthreads();

    int nseg = g_nseg[b];
    float4  ev4  = *(const float4*)&evs[4 * c];
    float4* outb = (float4*)(out + (size_t)b * T_ * D_);
    float4* msk4 = (float4*)(mask_out + (size_t)b * T_);

    // ---- Pass 1: mask + fill for inactive tiles (fire-and-forget stores) ----
    #pragma unroll 1
    for (int j = 0; j < NTILE; j++) {
        int t  = bx + j * GX;
        int s0 = t * ROWS;
        if (e < 8) {                       // mask for this tile's 32 words
            int w0 = s0 + 4 * e;
            float4 mv;
            mv.x = (w0     < nseg) ? 1.0f : 0.0f;
            mv.y = (w0 + 1 < nseg) ? 1.0f : 0.0f;
            mv.z = (w0 + 2 < nseg) ? 1.0f : 0.0f;
            mv.w = (w0 + 3 < nseg) ? 1.0f : 0.0f;
            msk4[t * 8 + e] = mv;
        }
        if (s0 >= nseg) {                  // fully-empty tile: constant rows
            float4* o4 = outb + (size_t)s0 * 64;
            #pragma unroll
            for (int r = r0; r < ROWS; r += 4) o4[r * 64 + c] = ev4;
        }
    }

    // ---- Pass 2: active tiles (pool -> GEMM -> LN -> store) ----
    #pragma unroll 1
    for (int j = 0; j < NTILE; j++) {
        int t    = bx + j * GX;
        int s0   = t * ROWS;
        int nact = nseg - s0; if (nact > ROWS) nact = ROWS;
        if (nact <= 0) continue;

        __syncthreads();                   // P/t0s reuse across iterations
        if (e < ROWS) {
            if (e < nact) {
                t0s[e] = g_start[b * MAXSEG + s0 + e];
                cns[e] = g_cnt[b * MAXSEG + s0 + e];
            } else { t0s[e] = 0; cns[e] = 0; }
        }
        __syncthreads();

        // Phase 1: segment-mean pooling (float4 streaming loads)
        for (int r = r0; r < ROWS; r += 4) {
            int cnt = cns[r];
            const float4* xp =
                (const float4*)(x + ((size_t)b * T_ + t0s[r]) * D_) + c;
            float4 a0 = {0,0,0,0}, a1 = {0,0,0,0}, a2 = {0,0,0,0}, a3 = {0,0,0,0};
            int k = 0;
            for (; k + 4 <= cnt; k += 4) {
                add4(a0, __ldcs(xp + (size_t)(k + 0) * 64));
                add4(a1, __ldcs(xp + (size_t)(k + 1) * 64));
                add4(a2, __ldcs(xp + (size_t)(k + 2) * 64));
                add4(a3, __ldcs(xp + (size_t)(k + 3) * 64));
            }
            for (; k < cnt; k++) add4(a0, __ldcs(xp + (size_t)k * 64));
            float inv = 1.0f / (float)(cnt > 0 ? cnt : 1);
            float4 mres;
            mres.x = (a0.x + a1.x + a2.x + a3.x) * inv;
            mres.y = (a0.y + a1.y + a2.y + a3.y) * inv;
            mres.z = (a0.z + a1.z + a2.z + a3.z) * inv;
            mres.w = (a0.w + a1.w + a2.w + a3.w) * inv;
            *(float4*)&P[r * D_ + 4 * c] = mres;
        }
        __syncthreads();

        // Phase 2: out[r][e] = P[r][:] . W[e][:] + b[e], packed f32x2
        unsigned long long acc2[ROWS];
        unsigned long long binit = (unsigned long long)__float_as_uint(bv);
        #pragma unroll
        for (int r = 0; r < ROWS; r++) acc2[r] = binit;

        const ulonglong2* W2 = (const ulonglong2*)(W + (size_t)e * D_);
        #pragma unroll 1
        for (int q = 0; q < D_ / 4; q++) {
            ulonglong2 wv = W2[q];
            const ulonglong2* Pq = (const ulonglong2*)&P[q * 4];
            #pragma unroll
            for (int r = 0; r < ROWS; r++) {
                ulonglong2 pv = Pq[r * (D_ / 4)];   // LDS.128 broadcast
                ffma2(acc2[r], pv.x, wv.x);
                ffma2(acc2[r], pv.y, wv.y);
            }
        }
        __syncthreads();

        // Phase 3: stash, LN stats, vectorized store
        #pragma unroll
        for (int r = 0; r < ROWS; r++) {
            unsigned long long a = acc2[r];
            P[r * D_ + e] = __uint_as_float((unsigned)a) +
                            __uint_as_float((unsigned)(a >> 32));
        }
        __syncthreads();

        for (int r = wid; r < ROWS; r += 8) {
            float ss = 0.f, ss2 = 0.f;
            #pragma unroll
            for (int jj = 0; jj < D_ / 32; jj++) {
                float v = P[r * D_ + lane + 32 * jj];
                ss += v; ss2 += v * v;
            }
            #pragma unroll
            for (int o = 16; o; o >>= 1) {
                ss  += __shfl_xor_sync(0xffffffffu, ss,  o);
                ss2 += __shfl_xor_sync(0xffffffffu, ss2, o);
            }
            if (lane == 0) {
                float m  = ss * (1.0f / D_);
                float va = fmaxf(ss2 * (1.0f / D_) - m * m, 0.0f);
                smu[r] = m;
                srs[r] = rsqrtf(va + LN_EPS);
            }
        }
        __syncthreads();

        float4 g4 = ((const float4*)gamma)[c];
        float4 b4 = ((const float4*)beta)[c];
        float4* o4 = outb + (size_t)s0 * 64;
        for (int r = r0; r < ROWS; r += 4) {
            float4 v;
            if (r < nact) {
                float4 p4 = *(const float4*)&P[r * D_ + 4 * c];
                float m = smu[r], rs = srs[r];
                v.x = (p4.x - m) * rs * g4.x + b4.x;
                v.y = (p4.y - m) * rs * g4.y + b4.y;
                v.z = (p4.z - m) * rs * g4.z + b4.z;
                v.w = (p4.w - m) * rs * g4.w + b4.w;
            } else {
                v = ev4;
            }
            o4[r * 64 + c] = v;
        }
    }
}

// ---------------------------------------------------------------------------
// Inputs (metadata order): x f32[16,8192,256], input_ids int64/int32[16,8192],
// W_proj f32[256,256], b_proj f32[256], gamma f32[256], beta f32[256].
// Output: concat(out f32[16,8192,256], mask f32[16,8192]).
// ---------------------------------------------------------------------------
extern "C" void kernel_launch(void* const* d_in, const int* in_sizes, int n_in,
                              void* d_out, int out_size) {
    (void)in_sizes; (void)n_in; (void)out_size;
    const float*        x   = (const float*)d_in[0];
    const unsigned int* ids = (const unsigned int*)d_in[1];
    const float*        W   = (const float*)d_in[2];
    const float*        bp  = (const float*)d_in[3];
    const float*        ga  = (const float*)d_in[4];
    const float*        be  = (const float*)d_in[5];
    float* out  = (float*)d_out;
    float* mask = out + (size_t)B_ * T_ * D_;

    seg_kernel<<<B_, 256>>>(ids);
    fused_kernel<<<dim3(GX, B_), 256>>>(x, W, bp, ga, be, out, mask);
}